// round 5
// baseline (speedup 1.0000x reference)
#include <cuda_runtime.h>
#include <stdint.h>
#include <math.h>

// Problem constants (fixed shapes for Model_17789754540572)
#define BATCH 32
#define SQ    2048
#define SKV   2048
#define DHEAD 128
#define BQ    64
#define BK    64
#define QSTR  132            // padded smem row stride (floats)
#define PSTR  68             // P tile row stride (floats)
#define NTHR  256

#define SM_Q  0
#define SM_K  (64 * QSTR)          // 8448
#define SM_V  (2 * 64 * QSTR)      // 16896
#define SM_P  SM_K                 // P aliases K region (64*68 <= 64*132)
#define SMEM_FLOATS (3 * 64 * QSTR)
#define SMEM_BYTES  (SMEM_FLOATS * 4)

// ---------------- threefry2x32 with key (0, 42)  (jax.random.key(42)) -------
__device__ __forceinline__ uint32_t rotl32(uint32_t x, int r) {
    return __funnelshift_l(x, x, r);
}
__device__ __forceinline__ void tf_round(uint32_t& x0, uint32_t& x1, int r) {
    x0 += x1; x1 = rotl32(x1, r); x1 ^= x0;
}
__device__ __forceinline__ uint2 threefry_0_42(uint32_t v0, uint32_t v1) {
    const uint32_t ks0 = 0u, ks1 = 42u, ks2 = 0x1BD11BDAu ^ 0u ^ 42u; // 0x1BD11BF0
    uint32_t x0 = v0 + ks0, x1 = v1 + ks1;
    tf_round(x0,x1,13); tf_round(x0,x1,15); tf_round(x0,x1,26); tf_round(x0,x1, 6);
    x0 += ks1; x1 += ks2 + 1u;
    tf_round(x0,x1,17); tf_round(x0,x1,29); tf_round(x0,x1,16); tf_round(x0,x1,24);
    x0 += ks2; x1 += ks0 + 2u;
    tf_round(x0,x1,13); tf_round(x0,x1,15); tf_round(x0,x1,26); tf_round(x0,x1, 6);
    x0 += ks0; x1 += ks1 + 3u;
    tf_round(x0,x1,17); tf_round(x0,x1,29); tf_round(x0,x1,16); tf_round(x0,x1,24);
    x0 += ks1; x1 += ks2 + 4u;
    tf_round(x0,x1,13); tf_round(x0,x1,15); tf_round(x0,x1,26); tf_round(x0,x1, 6);
    x0 += ks2; x1 += ks0 + 5u;
    return make_uint2(x0, x1);
}

// Partitionable-threefry keep mask (jax_threefry_partitionable=True):
//   i   = 64-bit flat index into (B,Sq,Skv); here i < 2^27 so hi(i)=0
//   o   = threefry2x32([0,42], v0=hi(i)=0, v1=lo(i)=i);  bits = o0 ^ o1
//   u   = bitcast((bits>>9)|0x3f800000) - 1;  keep = u < keep_p
__device__ __forceinline__ bool keep_mask(uint32_t idx) {
    uint2 r = threefry_0_42(0u, idx);
    uint32_t bits = r.x ^ r.y;
    float u = __uint_as_float((bits >> 9) | 0x3f800000u) - 1.0f;
    return u < 0.7f;
}

// ---------------------------------------------------------------------------
__global__ void __launch_bounds__(NTHR, 2)
attn_dropout_kernel(const float* __restrict__ q,
                    const float* __restrict__ k,
                    const float* __restrict__ v,
                    const float* __restrict__ scale,
                    float* __restrict__ out)
{
    extern __shared__ float smem[];
    float* Qs = smem + SM_Q;
    float* Ks = smem + SM_K;
    float* Vs = smem + SM_V;
    float* Ps = smem + SM_P;

    const int qtile = blockIdx.x;     // 0..31
    const int b     = blockIdx.y;     // 0..31
    const int t     = threadIdx.x;
    const int ty    = t >> 4;         // 0..15 : row group
    const int tx    = t & 15;         // 0..15 : col group

    const float sf = scale[b];
    const int   q0 = qtile * BQ;
    const uint32_t base_idx = ((uint32_t)b) << 22;   // b * Sq * Skv
    const float INV_KEEP = 1.0f / 0.7f;

    // ---- load Q tile [64][128] -> smem (padded stride) ----
    {
        const float4* gq = (const float4*)(q + ((size_t)b * SQ + q0) * DHEAD);
        #pragma unroll
        for (int it = 0; it < 8; it++) {
            int idx = it * NTHR + t;
            int r = idx >> 5, c = idx & 31;
            *(float4*)(Qs + r * QSTR + c * 4) = gq[r * 32 + c];
        }
    }

    float m_r[4], l_r[4], acc[4][8];
    #pragma unroll
    for (int i = 0; i < 4; i++) {
        m_r[i] = -INFINITY; l_r[i] = 0.0f;
        #pragma unroll
        for (int j = 0; j < 8; j++) acc[i][j] = 0.0f;
    }

    for (int kt = 0; kt < SKV / BK; kt++) {
        const int k0 = kt * BK;

        __syncthreads();   // prev PV done (Ps/Vs free); Q writes flushed (iter 0)

        // ---- load K,V tiles [64][128] -> smem ----
        {
            const float4* gk = (const float4*)(k + ((size_t)b * SKV + k0) * DHEAD);
            const float4* gv = (const float4*)(v + ((size_t)b * SKV + k0) * DHEAD);
            #pragma unroll
            for (int it = 0; it < 8; it++) {
                int idx = it * NTHR + t;
                int r = idx >> 5, c = idx & 31;
                *(float4*)(Ks + r * QSTR + c * 4) = gk[r * 32 + c];
                *(float4*)(Vs + r * QSTR + c * 4) = gv[r * 32 + c];
            }
        }
        __syncthreads();

        // ---- QK^T: s[i][j] = dot(Q[ty+16i], K[tx+16j]) over D=128 ----
        float s[4][4];
        #pragma unroll
        for (int i = 0; i < 4; i++)
            #pragma unroll
            for (int j = 0; j < 4; j++) s[i][j] = 0.0f;

        #pragma unroll 4
        for (int d4 = 0; d4 < 32; d4++) {
            float4 qv[4], kv[4];
            #pragma unroll
            for (int i = 0; i < 4; i++)
                qv[i] = *(const float4*)(Qs + (ty + 16 * i) * QSTR + d4 * 4);
            #pragma unroll
            for (int j = 0; j < 4; j++)
                kv[j] = *(const float4*)(Ks + (tx + 16 * j) * QSTR + d4 * 4);
            #pragma unroll
            for (int i = 0; i < 4; i++)
                #pragma unroll
                for (int j = 0; j < 4; j++) {
                    s[i][j] += qv[i].x * kv[j].x;
                    s[i][j] += qv[i].y * kv[j].y;
                    s[i][j] += qv[i].z * kv[j].z;
                    s[i][j] += qv[i].w * kv[j].w;
                }
        }

        // scale by per-batch factor
        #pragma unroll
        for (int i = 0; i < 4; i++)
            #pragma unroll
            for (int j = 0; j < 4; j++) s[i][j] *= sf;

        // ---- online softmax (rows reduced across the 16 lanes sharing ty) ----
        float p[4][4];
        float corr[4], mnew[4], rs[4];
        #pragma unroll
        for (int i = 0; i < 4; i++) {
            float mx = fmaxf(fmaxf(s[i][0], s[i][1]), fmaxf(s[i][2], s[i][3]));
            #pragma unroll
            for (int o = 8; o > 0; o >>= 1)
                mx = fmaxf(mx, __shfl_xor_sync(0xffffffffu, mx, o));
            mnew[i] = fmaxf(m_r[i], mx);
            corr[i] = __expf(m_r[i] - mnew[i]);   // exp(-inf)=0 on first tile
            float ssum = 0.0f;
            #pragma unroll
            for (int j = 0; j < 4; j++) {
                p[i][j] = __expf(s[i][j] - mnew[i]);
                ssum += p[i][j];
            }
            #pragma unroll
            for (int o = 8; o > 0; o >>= 1)
                ssum += __shfl_xor_sync(0xffffffffu, ssum, o);
            rs[i] = ssum;
        }
        #pragma unroll
        for (int i = 0; i < 4; i++) {
            l_r[i] = l_r[i] * corr[i] + rs[i];
            m_r[i] = mnew[i];
            #pragma unroll
            for (int j = 0; j < 8; j++) acc[i][j] *= corr[i];
        }

        __syncthreads();   // all K reads done before P overwrites the K buffer

        // ---- dropout + write P tile to smem ----
        #pragma unroll
        for (int i = 0; i < 4; i++) {
            const uint32_t row_idx = base_idx | ((uint32_t)(q0 + ty + 16 * i) << 11);
            #pragma unroll
            for (int j = 0; j < 4; j++) {
                uint32_t idx = row_idx | (uint32_t)(k0 + tx + 16 * j);
                float pd = keep_mask(idx) ? p[i][j] * INV_KEEP : 0.0f;
                Ps[(ty + 16 * i) * PSTR + (tx + 16 * j)] = pd;
            }
        }
        __syncthreads();   // P ready

        // ---- PV: acc[i][*] += P[row][c] * V[c][cols of tx] ----
        #pragma unroll 4
        for (int c = 0; c < BK; c++) {
            float pv[4];
            #pragma unroll
            for (int i = 0; i < 4; i++)
                pv[i] = Ps[(ty + 16 * i) * PSTR + c];
            float4 v0 = *(const float4*)(Vs + c * QSTR + tx * 4);
            float4 v1 = *(const float4*)(Vs + c * QSTR + 64 + tx * 4);
            #pragma unroll
            for (int i = 0; i < 4; i++) {
                acc[i][0] += pv[i] * v0.x;
                acc[i][1] += pv[i] * v0.y;
                acc[i][2] += pv[i] * v0.z;
                acc[i][3] += pv[i] * v0.w;
                acc[i][4] += pv[i] * v1.x;
                acc[i][5] += pv[i] * v1.y;
                acc[i][6] += pv[i] * v1.z;
                acc[i][7] += pv[i] * v1.w;
            }
        }
    }

    // ---- epilogue: normalize and write out ----
    #pragma unroll
    for (int i = 0; i < 4; i++) {
        float inv_l = 1.0f / l_r[i];
        float* orow = out + ((size_t)b * SQ + (q0 + ty + 16 * i)) * DHEAD;
        float4 o0 = make_float4(acc[i][0] * inv_l, acc[i][1] * inv_l,
                                acc[i][2] * inv_l, acc[i][3] * inv_l);
        float4 o1 = make_float4(acc[i][4] * inv_l, acc[i][5] * inv_l,
                                acc[i][6] * inv_l, acc[i][7] * inv_l);
        *(float4*)(orow + 4 * tx)      = o0;
        *(float4*)(orow + 64 + 4 * tx) = o1;
    }
}

extern "C" void kernel_launch(void* const* d_in, const int* in_sizes, int n_in,
                              void* d_out, int out_size)
{
    const float* q  = (const float*)d_in[0];
    const float* k  = (const float*)d_in[1];
    const float* v  = (const float*)d_in[2];
    const float* sf = (const float*)d_in[3];
    float* out = (float*)d_out;

    cudaFuncSetAttribute(attn_dropout_kernel,
                         cudaFuncAttributeMaxDynamicSharedMemorySize, SMEM_BYTES);

    dim3 grid(SQ / BQ, BATCH);
    attn_dropout_kernel<<<grid, NTHR, SMEM_BYTES>>>(q, k, v, sf, out);
}

// round 6
// speedup vs baseline: 1.0504x; 1.0504x over previous
#include <cuda_runtime.h>
#include <stdint.h>
#include <math.h>

// Problem constants (fixed shapes for Model_17789754540572)
#define BATCH 32
#define SQ    2048
#define SKV   2048
#define DHEAD 128
#define BQ    64
#define BK    64
#define QSTR  132            // padded smem row stride (floats)
#define PSTR  68             // P tile row stride (floats)
#define NTHR  256

#define SM_Q  0
#define SM_K  (64 * QSTR)          // 8448
#define SM_V  (2 * 64 * QSTR)      // 16896
#define SM_P  SM_K                 // P aliases K region (64*68 <= 64*132)
#define SMEM_FLOATS (3 * 64 * QSTR)
#define SMEM_BYTES  (SMEM_FLOATS * 4)

// ---------------- packed f32x2 helpers (sm_103a FFMA2 path) ----------------
typedef unsigned long long u64t;

#define FMA2(d, a, b, c) \
    asm("fma.rn.f32x2 %0, %1, %2, %3;" : "=l"(d) : "l"(a), "l"(b), "l"(c))
#define MUL2(d, a, b) \
    asm("mul.rn.f32x2 %0, %1, %2;" : "=l"(d) : "l"(a), "l"(b))

__device__ __forceinline__ u64t pack2(float lo, float hi) {
    u64t r;
    asm("mov.b64 %0, {%1, %2};" : "=l"(r) : "f"(lo), "f"(hi));
    return r;
}
__device__ __forceinline__ float2 unpack2(u64t v) {
    float lo, hi;
    asm("mov.b64 {%0, %1}, %2;" : "=f"(lo), "=f"(hi) : "l"(v));
    return make_float2(lo, hi);
}

// ---------------- threefry2x32 with key (0, 42)  (jax.random.key(42)) -------
__device__ __forceinline__ uint32_t rotl32(uint32_t x, int r) {
    return __funnelshift_l(x, x, r);
}
__device__ __forceinline__ void tf_round(uint32_t& x0, uint32_t& x1, int r) {
    x0 += x1; x1 = rotl32(x1, r); x1 ^= x0;
}
__device__ __forceinline__ uint2 threefry_0_42(uint32_t v0, uint32_t v1) {
    const uint32_t ks0 = 0u, ks1 = 42u, ks2 = 0x1BD11BDAu ^ 0u ^ 42u; // 0x1BD11BF0
    uint32_t x0 = v0 + ks0, x1 = v1 + ks1;
    tf_round(x0,x1,13); tf_round(x0,x1,15); tf_round(x0,x1,26); tf_round(x0,x1, 6);
    x0 += ks1; x1 += ks2 + 1u;
    tf_round(x0,x1,17); tf_round(x0,x1,29); tf_round(x0,x1,16); tf_round(x0,x1,24);
    x0 += ks2; x1 += ks0 + 2u;
    tf_round(x0,x1,13); tf_round(x0,x1,15); tf_round(x0,x1,26); tf_round(x0,x1, 6);
    x0 += ks0; x1 += ks1 + 3u;
    tf_round(x0,x1,17); tf_round(x0,x1,29); tf_round(x0,x1,16); tf_round(x0,x1,24);
    x0 += ks1; x1 += ks2 + 4u;
    tf_round(x0,x1,13); tf_round(x0,x1,15); tf_round(x0,x1,26); tf_round(x0,x1, 6);
    x0 += ks2; x1 += ks0 + 5u;
    return make_uint2(x0, x1);
}

// Partitionable-threefry keep mask (jax_threefry_partitionable=True)
__device__ __forceinline__ bool keep_mask(uint32_t idx) {
    uint2 r = threefry_0_42(0u, idx);
    uint32_t bits = r.x ^ r.y;
    float u = __uint_as_float((bits >> 9) | 0x3f800000u) - 1.0f;
    return u < 0.7f;
}

// ---------------------------------------------------------------------------
__global__ void __launch_bounds__(NTHR, 2)
attn_dropout_kernel(const float* __restrict__ q,
                    const float* __restrict__ k,
                    const float* __restrict__ v,
                    const float* __restrict__ scale,
                    float* __restrict__ out)
{
    extern __shared__ float smem[];
    float* Qs = smem + SM_Q;
    float* Ks = smem + SM_K;
    float* Vs = smem + SM_V;
    float* Ps = smem + SM_P;

    const int qtile = blockIdx.x;     // 0..31
    const int b     = blockIdx.y;     // 0..31
    const int t     = threadIdx.x;
    const int ty    = t >> 4;         // 0..15 : row group
    const int tx    = t & 15;         // 0..15 : col group

    const float sf = scale[b];
    const int   q0 = qtile * BQ;
    const uint32_t base_idx = ((uint32_t)b) << 22;   // b * Sq * Skv
    const float INV_KEEP = 1.0f / 0.7f;

    // ---- load Q tile [64][128] -> smem (padded stride) ----
    {
        const float4* gq = (const float4*)(q + ((size_t)b * SQ + q0) * DHEAD);
        #pragma unroll
        for (int it = 0; it < 8; it++) {
            int idx = it * NTHR + t;
            int r = idx >> 5, c = idx & 31;
            *(float4*)(Qs + r * QSTR + c * 4) = gq[r * 32 + c];
        }
    }

    float m_r[4], l_r[4];
    u64t acc2[4][4];                   // packed pairs of adjacent output cols
    #pragma unroll
    for (int i = 0; i < 4; i++) {
        m_r[i] = -INFINITY; l_r[i] = 0.0f;
        #pragma unroll
        for (int j = 0; j < 4; j++) acc2[i][j] = 0ull;
    }

    for (int kt = 0; kt < SKV / BK; kt++) {
        const int k0 = kt * BK;

        __syncthreads();   // prev PV done (Ps/Vs free); Q writes flushed (iter 0)

        // ---- load K,V tiles [64][128] -> smem ----
        {
            const float4* gk = (const float4*)(k + ((size_t)b * SKV + k0) * DHEAD);
            const float4* gv = (const float4*)(v + ((size_t)b * SKV + k0) * DHEAD);
            #pragma unroll
            for (int it = 0; it < 8; it++) {
                int idx = it * NTHR + t;
                int r = idx >> 5, c = idx & 31;
                *(float4*)(Ks + r * QSTR + c * 4) = gk[r * 32 + c];
                *(float4*)(Vs + r * QSTR + c * 4) = gv[r * 32 + c];
            }
        }
        __syncthreads();

        // ---- QK^T (packed f32x2 along d): s2 = even/odd-d partial sums ----
        u64t s2[4][4];
        #pragma unroll
        for (int i = 0; i < 4; i++)
            #pragma unroll
            for (int j = 0; j < 4; j++) s2[i][j] = 0ull;

        #pragma unroll 4
        for (int d4 = 0; d4 < 32; d4++) {
            ulonglong2 qv[4], kv[4];   // .x = packed(d,d+1), .y = packed(d+2,d+3)
            #pragma unroll
            for (int i = 0; i < 4; i++)
                qv[i] = *(const ulonglong2*)(Qs + (ty + 16 * i) * QSTR + d4 * 4);
            #pragma unroll
            for (int j = 0; j < 4; j++)
                kv[j] = *(const ulonglong2*)(Ks + (tx + 16 * j) * QSTR + d4 * 4);
            #pragma unroll
            for (int i = 0; i < 4; i++)
                #pragma unroll
                for (int j = 0; j < 4; j++) {
                    FMA2(s2[i][j], qv[i].x, kv[j].x, s2[i][j]);
                    FMA2(s2[i][j], qv[i].y, kv[j].y, s2[i][j]);
                }
        }

        // reduce packed halves, apply per-batch scale
        float s[4][4];
        #pragma unroll
        for (int i = 0; i < 4; i++)
            #pragma unroll
            for (int j = 0; j < 4; j++) {
                float2 h = unpack2(s2[i][j]);
                s[i][j] = (h.x + h.y) * sf;
            }

        // ---- online softmax (rows reduced across the 16 lanes sharing ty) ----
        float p[4][4];
        float corr[4], mnew[4], rs[4];
        #pragma unroll
        for (int i = 0; i < 4; i++) {
            float mx = fmaxf(fmaxf(s[i][0], s[i][1]), fmaxf(s[i][2], s[i][3]));
            #pragma unroll
            for (int o = 8; o > 0; o >>= 1)
                mx = fmaxf(mx, __shfl_xor_sync(0xffffffffu, mx, o));
            mnew[i] = fmaxf(m_r[i], mx);
            corr[i] = __expf(m_r[i] - mnew[i]);   // exp(-inf)=0 on first tile
            float ssum = 0.0f;
            #pragma unroll
            for (int j = 0; j < 4; j++) {
                p[i][j] = __expf(s[i][j] - mnew[i]);
                ssum += p[i][j];
            }
            #pragma unroll
            for (int o = 8; o > 0; o >>= 1)
                ssum += __shfl_xor_sync(0xffffffffu, ssum, o);
            rs[i] = ssum;
        }
        #pragma unroll
        for (int i = 0; i < 4; i++) {
            l_r[i] = l_r[i] * corr[i] + rs[i];
            m_r[i] = mnew[i];
            u64t c2 = pack2(corr[i], corr[i]);
            #pragma unroll
            for (int j = 0; j < 4; j++) MUL2(acc2[i][j], acc2[i][j], c2);
        }

        __syncthreads();   // all K reads done before P overwrites the K buffer

        // ---- dropout + write P tile to smem ----
        #pragma unroll
        for (int i = 0; i < 4; i++) {
            const uint32_t row_idx = base_idx | ((uint32_t)(q0 + ty + 16 * i) << 11);
            #pragma unroll
            for (int j = 0; j < 4; j++) {
                uint32_t idx = row_idx | (uint32_t)(k0 + tx + 16 * j);
                float pd = keep_mask(idx) ? p[i][j] * INV_KEEP : 0.0f;
                Ps[(ty + 16 * i) * PSTR + (tx + 16 * j)] = pd;
            }
        }
        __syncthreads();   // P ready

        // ---- PV (packed f32x2 along output cols) ----
        #pragma unroll 4
        for (int c = 0; c < BK; c++) {
            u64t pb[4];
            #pragma unroll
            for (int i = 0; i < 4; i++) {
                float pv = Ps[(ty + 16 * i) * PSTR + c];
                pb[i] = pack2(pv, pv);
            }
            ulonglong2 v0 = *(const ulonglong2*)(Vs + c * QSTR + tx * 4);
            ulonglong2 v1 = *(const ulonglong2*)(Vs + c * QSTR + 64 + tx * 4);
            #pragma unroll
            for (int i = 0; i < 4; i++) {
                FMA2(acc2[i][0], pb[i], v0.x, acc2[i][0]);
                FMA2(acc2[i][1], pb[i], v0.y, acc2[i][1]);
                FMA2(acc2[i][2], pb[i], v1.x, acc2[i][2]);
                FMA2(acc2[i][3], pb[i], v1.y, acc2[i][3]);
            }
        }
    }

    // ---- epilogue: normalize and write out ----
    #pragma unroll
    for (int i = 0; i < 4; i++) {
        float inv_l = 1.0f / l_r[i];
        u64t il2 = pack2(inv_l, inv_l);
        float* orow = out + ((size_t)b * SQ + (q0 + ty + 16 * i)) * DHEAD;
        u64t o00, o01, o10, o11;
        MUL2(o00, acc2[i][0], il2);
        MUL2(o01, acc2[i][1], il2);
        MUL2(o10, acc2[i][2], il2);
        MUL2(o11, acc2[i][3], il2);
        ulonglong2 w0; w0.x = o00; w0.y = o01;
        ulonglong2 w1; w1.x = o10; w1.y = o11;
        *(ulonglong2*)(orow + 4 * tx)      = w0;
        *(ulonglong2*)(orow + 64 + 4 * tx) = w1;
    }
}

extern "C" void kernel_launch(void* const* d_in, const int* in_sizes, int n_in,
                              void* d_out, int out_size)
{
    const float* q  = (const float*)d_in[0];
    const float* k  = (const float*)d_in[1];
    const float* v  = (const float*)d_in[2];
    const float* sf = (const float*)d_in[3];
    float* out = (float*)d_out;

    cudaFuncSetAttribute(attn_dropout_kernel,
                         cudaFuncAttributeMaxDynamicSharedMemorySize, SMEM_BYTES);

    dim3 grid(SQ / BQ, BATCH);
    attn_dropout_kernel<<<grid, NTHR, SMEM_BYTES>>>(q, k, v, sf, out);
}